// round 16
// baseline (speedup 1.0000x reference)
#include <cuda_runtime.h>
#include <cuda_bf16.h>
#include <cstdint>

#define N_SRC     100000
#define N_NODES   1000000
#define N_NEIGH   20
#define RAW_DIM   256
#define MSG       128

#define TM        32           // 100000 = 32 * 3125 exactly
#define THREADS   192          // 4 MMA warps + 2 gather warps
#define NMMA      128

// A tile: [32 rows][264 bf16] stride 528 B (33*16B -> ldmatrix conflict-free)
#define ASTR      528
// B tiles: [128 k][136 bf16] stride 272 B (17*16B); two buffers, ping-pong
#define BSTR      272

#define OFF_AH    0                     // 32*528 = 16896
#define OFF_AL    16896                 // -> 33792
#define OFF_B0    33792                 // 34816 -> 68608
#define OFF_B1    68608                 // 34816 -> 103424
#define OFF_NEI   103424                // 2560 -> 105984
#define OFF_B1S   105984
#define OFF_B2S   106496
#define OFF_BNS   107008
#define OFF_IS64  107520
#define SMEM_REQ  107536

// pre-converted weights, laid out exactly like the smem B tiles
__device__ __align__(16) __nv_bfloat16 g_W1h[256 * 136];
__device__ __align__(16) __nv_bfloat16 g_W1l[256 * 136];
__device__ __align__(16) __nv_bfloat16 g_W2h[128 * 136];
__device__ __align__(16) __nv_bfloat16 g_W2l[128 * 136];
__device__ __align__(16) __nv_bfloat16 g_Wnh[128 * 136];
__device__ __align__(16) __nv_bfloat16 g_Wnl[128 * 136];

__device__ int g_is64;

__device__ __forceinline__ unsigned short bf_hi(float x) {
    return __bfloat16_as_ushort(__float2bfloat16(x));
}
__device__ __forceinline__ unsigned short bf_lo(float x) {
    __nv_bfloat16 h = __float2bfloat16(x);
    return __bfloat16_as_ushort(__float2bfloat16(x - __bfloat162float(h)));
}
__device__ __forceinline__ uint32_t pack2(unsigned short a, unsigned short b) {
    return (uint32_t)a | ((uint32_t)b << 16);
}

// prep: weight conversion + (block 0, warp 0) index-dtype detection.
__global__ void prep_weights(const float* __restrict__ W1,
                             const float* __restrict__ W2,
                             const float* __restrict__ Wn,
                             const long long* __restrict__ neigh) {
    if (blockIdx.x == 0 && threadIdx.x < 32) {
        int lane = threadIdx.x;
        long long v0 = neigh[lane];
        long long v1 = neigh[lane + 32];
        int bad = (v0 < 0 || v0 >= (long long)N_NODES ||
                   v1 < 0 || v1 >= (long long)N_NODES) ? 1 : 0;
        unsigned m = __ballot_sync(0xFFFFFFFFu, bad);
        if (lane == 0) g_is64 = m ? 0 : 1;
    }
    int i = blockIdx.x * blockDim.x + threadIdx.x;
    if (i < 256 * 128) {
        int r = i >> 7, c = i & 127;
        float v = W1[i];
        g_W1h[r * 136 + c] = __ushort_as_bfloat16(bf_hi(v));
        g_W1l[r * 136 + c] = __ushort_as_bfloat16(bf_lo(v));
    } else if (i < 256 * 128 + 128 * 128) {
        int j = i - 256 * 128;
        int r = j >> 7, c = j & 127;
        float v = W2[j];
        g_W2h[r * 136 + c] = __ushort_as_bfloat16(bf_hi(v));
        g_W2l[r * 136 + c] = __ushort_as_bfloat16(bf_lo(v));
    } else if (i < 256 * 128 + 2 * 128 * 128) {
        int j = i - 256 * 128 - 128 * 128;
        int r = j >> 7, c = j & 127;
        float v = Wn[j];
        g_Wnh[r * 136 + c] = __ushort_as_bfloat16(bf_hi(v));
        g_Wnl[r * 136 + c] = __ushort_as_bfloat16(bf_lo(v));
    }
}

__device__ __forceinline__ uint32_t smem_u32(const void* p) {
    uint32_t a;
    asm("{ .reg .u64 t; cvta.to.shared.u64 t, %1; cvt.u32.u64 %0, t; }" : "=r"(a) : "l"(p));
    return a;
}

#define BARX(id, cnt) asm volatile("bar.sync %0, %1;" :: "r"(id), "r"(cnt) : "memory")
#define CP_COMMIT()   asm volatile("cp.async.commit_group;" ::: "memory")
#define CP_WAIT0()    asm volatile("cp.async.wait_group 0;" ::: "memory")

#define LDSM_X4(r, addr) \
    asm volatile("ldmatrix.sync.aligned.m8n8.x4.shared.b16 {%0,%1,%2,%3}, [%4];" \
        : "=r"((r)[0]), "=r"((r)[1]), "=r"((r)[2]), "=r"((r)[3]) : "r"(addr))

#define LDSM_X4T(r, addr) \
    asm volatile("ldmatrix.sync.aligned.m8n8.x4.trans.shared.b16 {%0,%1,%2,%3}, [%4];" \
        : "=r"((r)[0]), "=r"((r)[1]), "=r"((r)[2]), "=r"((r)[3]) : "r"(addr))

#define MMA16816(ac, a, b0, b1) \
    asm volatile("mma.sync.aligned.m16n8k16.row.col.f32.bf16.bf16.f32 " \
        "{%0,%1,%2,%3}, {%4,%5,%6,%7}, {%8,%9}, {%0,%1,%2,%3};" \
        : "+f"((ac)[0]), "+f"((ac)[1]), "+f"((ac)[2]), "+f"((ac)[3]) \
        : "r"((a)[0]), "r"((a)[1]), "r"((a)[2]), "r"((a)[3]), "r"(b0), "r"(b1))

// async copy of one pre-converted B tile (34816 B) into a smem buffer.
__device__ __forceinline__ void issue_B(uint32_t smem_dst,
                                        const __nv_bfloat16* __restrict__ g,
                                        int k0, int tid) {
    const char* src = (const char*)(g + k0 * 136);
    #pragma unroll
    for (int i = 0; i < 17; i++) {
        int e = tid + i * NMMA;            // 0..2175
        asm volatile("cp.async.cg.shared.global [%0], [%1], 16;"
                     :: "r"(smem_dst + e * 16), "l"(src + (size_t)e * 16));
    }
}

// pair product over one K=128 B tile: acc += Ah@B + Al@B
__device__ __forceinline__ void run_pair(
    float acc[8][4], uint32_t sAh, uint32_t sAl, uint32_t sB,
    int lane, int r0, int c0, int aoff)
{
    const int arow = lane & 15;
    const int aka  = (lane >> 4) << 3;
    const int bk   = (lane & 7) + ((lane >> 3) & 1) * 8;
    const int bn   = ((lane >> 4) & 1) * 8;
    #pragma unroll
    for (int ks = 0; ks < 8; ks++) {
        const int k0 = ks * 16;
        uint32_t ah[4], al[4], b[4][4];
        {
            uint32_t off = (uint32_t)((r0 + arow) * ASTR + (aoff + k0 + aka) * 2);
            LDSM_X4(ah, sAh + off);
            LDSM_X4(al, sAl + off);
        }
        #pragma unroll
        for (int ng = 0; ng < 4; ng++) {
            uint32_t off = (uint32_t)((k0 + bk) * BSTR + (c0 + ng * 16 + bn) * 2);
            LDSM_X4T(b[ng], sB + off);
        }
        #pragma unroll
        for (int nt = 0; nt < 8; nt++) {
            const int ng = nt >> 1, s2 = (nt & 1) * 2;
            MMA16816(acc[nt], ah, b[ng][s2], b[ng][s2 + 1]);
            MMA16816(acc[nt], al, b[ng][s2], b[ng][s2 + 1]);
        }
    }
}

// single product: acc += Ah@B
__device__ __forceinline__ void run_single(
    float acc[8][4], uint32_t sAh, uint32_t sB,
    int lane, int r0, int c0, int aoff)
{
    const int arow = lane & 15;
    const int aka  = (lane >> 4) << 3;
    const int bk   = (lane & 7) + ((lane >> 3) & 1) * 8;
    const int bn   = ((lane >> 4) & 1) * 8;
    #pragma unroll
    for (int ks = 0; ks < 8; ks++) {
        const int k0 = ks * 16;
        uint32_t ah[4], b[4][4];
        {
            uint32_t off = (uint32_t)((r0 + arow) * ASTR + (aoff + k0 + aka) * 2);
            LDSM_X4(ah, sAh + off);
        }
        #pragma unroll
        for (int ng = 0; ng < 4; ng++) {
            uint32_t off = (uint32_t)((k0 + bk) * BSTR + (c0 + ng * 16 + bn) * 2);
            LDSM_X4T(b[ng], sB + off);
        }
        #pragma unroll
        for (int nt = 0; nt < 8; nt++) {
            const int ng = nt >> 1, s2 = (nt & 1) * 2;
            MMA16816(acc[nt], ah, b[ng][s2], b[ng][s2 + 1]);
        }
    }
}

// full-K A tile: raw[row0+m][0..255] -> hi/lo bf16, by 128 MMA threads
__device__ __forceinline__ void load_A_full(char* sm, const float* __restrict__ raw,
                                            int row0, int tid) {
    #pragma unroll 4
    for (int i = tid; i < TM * 64; i += NMMA) {
        int m  = i >> 6;
        int k4 = (i & 63) << 2;
        float4 v = *(const float4*)&raw[(size_t)(row0 + m) * RAW_DIM + k4];
        uint2 hp = make_uint2(pack2(bf_hi(v.x), bf_hi(v.y)), pack2(bf_hi(v.z), bf_hi(v.w)));
        uint2 lp = make_uint2(pack2(bf_lo(v.x), bf_lo(v.y)), pack2(bf_lo(v.z), bf_lo(v.w)));
        *(uint2*)(sm + OFF_AH + m * ASTR + k4 * 2) = hp;
        *(uint2*)(sm + OFF_AL + m * ASTR + k4 * 2) = lp;
    }
}

// fp32 'a' staging in the unused upper-K bytes (256..511) of the A tiles
__device__ __forceinline__ uint32_t stg_addr(int li) {
    return (uint32_t)(((li >> 11) ? OFF_AL : OFF_AH)
                      + ((li >> 6) & 31) * ASTR + 256 + (li & 63) * 4);
}

extern __shared__ char sm[];

__global__ __launch_bounds__(THREADS, 2)
void fused_ws7_kernel(
    const float* __restrict__ raw,
    const void*  __restrict__ neigh,
    const float* __restrict__ memory,
    const float* __restrict__ b1,
    const float* __restrict__ b2,
    const float* __restrict__ bn,
    float*       __restrict__ out)
{
    const uint32_t smb = smem_u32(sm);
    const int tid  = threadIdx.x;
    const int lane = tid & 31;
    const int wid  = tid >> 5;
    const int row0 = blockIdx.x * TM;

    if (tid == 0) *(int*)(sm + OFF_IS64) = g_is64;
    if (tid < 128) {
        ((float*)(sm + OFF_B1S))[tid] = b1[tid];
        ((float*)(sm + OFF_B2S))[tid] = b2[tid];
        ((float*)(sm + OFF_BNS))[tid] = bn[tid];
    }
    __syncthreads();

    // ---- neighbor indices -> smem (all threads) ----
    {
        int is64 = *(volatile int*)(sm + OFF_IS64);
        int* nbw = (int*)(sm + OFF_NEI);
        if (is64) {
            const long long* p = (const long long*)neigh;
            for (int i = tid; i < TM * N_NEIGH; i += THREADS)
                nbw[i] = (int)p[(size_t)row0 * N_NEIGH + i];
        } else {
            const int* p = (const int*)neigh;
            for (int i = tid; i < TM * N_NEIGH; i += THREADS)
                nbw[i] = p[(size_t)row0 * N_NEIGH + i];
        }
    }
    __syncthreads();

    const uint32_t AH = smb + OFF_AH, AL = smb + OFF_AL;
    const uint32_t B0 = smb + OFF_B0, B1T = smb + OFF_B1;

    if (wid < 4) {
        // ================== MMA warps (tid 0..127) ==================
        const int r0 = (wid >> 1) * 16;
        const int c0 = (wid & 1) * 64;

        float acc[8][4];
        #pragma unroll
        for (int nt = 0; nt < 8; nt++)
            #pragma unroll
            for (int e = 0; e < 4; e++) acc[nt][e] = 0.f;

        // ---- GEMM1: raw @ W1 (K=256), B tiles ping-ponged via cp.async ----
        issue_B(B0, g_W1h, 0, tid);   CP_COMMIT();
        load_A_full(sm, raw, row0, tid);
        CP_WAIT0(); BARX(1, NMMA);

        issue_B(B1T, g_W1l, 0, tid);  CP_COMMIT();
        run_pair(acc, AH, AL, B0, lane, r0, c0, 0);
        CP_WAIT0(); BARX(1, NMMA);

        issue_B(B0, g_W1h, 128, tid); CP_COMMIT();
        run_single(acc, AH, B1T, lane, r0, c0, 0);
        CP_WAIT0(); BARX(1, NMMA);

        issue_B(B1T, g_W1l, 128, tid); CP_COMMIT();
        run_pair(acc, AH, AL, B0, lane, r0, c0, 128);
        CP_WAIT0(); BARX(1, NMMA);

        issue_B(B0, g_W2h, 0, tid);   CP_COMMIT();
        run_single(acc, AH, B1T, lane, r0, c0, 128);

        // ---- epilogue 1: h = relu(C1 + b1) -> A cols 0..127 ----
        {
            const float* sb1 = (const float*)(sm + OFF_B1S);
            const int qr = lane >> 2, qc = (lane & 3) * 2;
            #pragma unroll
            for (int nt = 0; nt < 8; nt++) {
                int R = r0 + qr;
                int C = c0 + nt * 8 + qc;
                float v0 = fmaxf(acc[nt][0] + sb1[C],     0.f);
                float v1 = fmaxf(acc[nt][1] + sb1[C + 1], 0.f);
                float v2 = fmaxf(acc[nt][2] + sb1[C],     0.f);
                float v3 = fmaxf(acc[nt][3] + sb1[C + 1], 0.f);
                *(uint32_t*)(sm + OFF_AH + R * ASTR + C * 2)       = pack2(bf_hi(v0), bf_hi(v1));
                *(uint32_t*)(sm + OFF_AL + R * ASTR + C * 2)       = pack2(bf_lo(v0), bf_lo(v1));
                *(uint32_t*)(sm + OFF_AH + (R + 8) * ASTR + C * 2) = pack2(bf_hi(v2), bf_hi(v3));
                *(uint32_t*)(sm + OFF_AL + (R + 8) * ASTR + C * 2) = pack2(bf_lo(v2), bf_lo(v3));
                acc[nt][0] = acc[nt][1] = acc[nt][2] = acc[nt][3] = 0.f;
            }
        }
        CP_WAIT0(); BARX(1, NMMA);     // publishes h tiles + W2h

        // ---- GEMM2: h @ W2 ----
        issue_B(B1T, g_W2l, 0, tid);  CP_COMMIT();
        run_pair(acc, AH, AL, B0, lane, r0, c0, 0);
        CP_WAIT0(); BARX(1, NMMA);

        issue_B(B0, g_Wnh, 0, tid);   CP_COMMIT();
        run_single(acc, AH, B1T, lane, r0, c0, 0);
        CP_WAIT0();                    // Wnh landed in B0

        BARX(2, THREADS);   // A tiles free for agg; gather sums ready

        // ---- stage a = relu(C2 + b2) into upper-K bytes ----
        {
            const float* sb2 = (const float*)(sm + OFF_B2S);
            const int qc = (lane & 3) * 2;
            #pragma unroll
            for (int nt = 0; nt < 8; nt++) {
                int C = c0 + nt * 8 + qc;
                *(float*)(sm + stg_addr((nt * 4 + 0) * NMMA + tid)) = fmaxf(acc[nt][0] + sb2[C],     0.f);
                *(float*)(sm + stg_addr((nt * 4 + 1) * NMMA + tid)) = fmaxf(acc[nt][1] + sb2[C + 1], 0.f);
                *(float*)(sm + stg_addr((nt * 4 + 2) * NMMA + tid)) = fmaxf(acc[nt][2] + sb2[C],     0.f);
                *(float*)(sm + stg_addr((nt * 4 + 3) * NMMA + tid)) = fmaxf(acc[nt][3] + sb2[C + 1], 0.f);
                acc[nt][0] = acc[nt][1] = acc[nt][2] = acc[nt][3] = 0.f;
            }
        }
        issue_B(B1T, g_Wnl, 0, tid);  CP_COMMIT();

        BARX(3, THREADS);   // agg tiles published by gather warps

        // ---- GEMM3: agg @ Wn ----
        run_pair(acc, AH, AL, B0, lane, r0, c0, 0);
        CP_WAIT0(); BARX(1, NMMA);     // Wnl ready
        run_single(acc, AH, B1T, lane, r0, c0, 0);

        // ---- final: out = a + relu(C3 + bn) ----
        {
            const float* sbn = (const float*)(sm + OFF_BNS);
            const int qr = lane >> 2, qc = (lane & 3) * 2;
            #pragma unroll
            for (int nt = 0; nt < 8; nt++) {
                int R = r0 + qr;
                int C = c0 + nt * 8 + qc;
                float a0 = *(const float*)(sm + stg_addr((nt * 4 + 0) * NMMA + tid));
                float a1 = *(const float*)(sm + stg_addr((nt * 4 + 1) * NMMA + tid));
                float a2 = *(const float*)(sm + stg_addr((nt * 4 + 2) * NMMA + tid));
                float a3 = *(const float*)(sm + stg_addr((nt * 4 + 3) * NMMA + tid));
                float o0 = a0 + fmaxf(acc[nt][0] + sbn[C],     0.f);
                float o1 = a1 + fmaxf(acc[nt][1] + sbn[C + 1], 0.f);
                float o2 = a2 + fmaxf(acc[nt][2] + sbn[C],     0.f);
                float o3 = a3 + fmaxf(acc[nt][3] + sbn[C + 1], 0.f);
                *(float2*)&out[(size_t)(row0 + R) * MSG + C]     = make_float2(o0, o1);
                *(float2*)&out[(size_t)(row0 + R + 8) * MSG + C] = make_float2(o2, o3);
            }
        }
    } else {
        // ================== gather warps (wid 4,5), 16 rows each ==================
        const int gw = wid - 4;
        const int* nb = (const int*)(sm + OFF_NEI);
        const float4* mem4 = (const float4*)memory;

        // ---- phase 0: L2 prefetch sweep of all 320 (row,neighbor) slices ----
        // Resident-gather footprint: 296 CTAs x 327KB = 96MB < 126MB L2, so
        // prefetched lines survive until the register sum loop consumes them.
        // No destination registers -> DRAM-side MLP limited only by queues.
        {
            const char* mbase = (const char*)memory;
            const int base = gw * 16 * N_NEIGH;
            #pragma unroll 2
            for (int i = lane; i < 16 * N_NEIGH; i += 32) {
                const char* p = mbase + (size_t)nb[base + i] * 512;
                asm volatile("prefetch.global.L2 [%0];" :: "l"(p));
                asm volatile("prefetch.global.L2 [%0];" :: "l"(p + 128));
                asm volatile("prefetch.global.L2 [%0];" :: "l"(p + 256));
                asm volatile("prefetch.global.L2 [%0];" :: "l"(p + 384));
            }
        }

        // ---- phase 1: register sum loop (now mostly L2 hits) ----
        float4 sums[16];
        #pragma unroll
        for (int r = 0; r < 16; r++) {
            const int row = gw * 16 + r;
            float4 s0 = make_float4(0.f, 0.f, 0.f, 0.f);
            float4 s1 = make_float4(0.f, 0.f, 0.f, 0.f);
            #pragma unroll
            for (int j = 0; j < N_NEIGH; j += 2) {
                int nd0 = nb[row * N_NEIGH + j];
                int nd1 = nb[row * N_NEIGH + j + 1];
                float4 v0 = __ldg(&mem4[(size_t)nd0 * 32 + lane]);
                float4 v1 = __ldg(&mem4[(size_t)nd1 * 32 + lane]);
                s0.x += v0.x; s0.y += v0.y; s0.z += v0.z; s0.w += v0.w;
                s1.x += v1.x; s1.y += v1.y; s1.z += v1.z; s1.w += v1.w;
            }
            const float inv = 1.0f / (float)N_NEIGH;
            sums[r] = make_float4((s0.x + s1.x) * inv, (s0.y + s1.y) * inv,
                                  (s0.z + s1.z) * inv, (s0.w + s1.w) * inv);
        }

        BARX(2, THREADS);   // wait until GEMM2 stops reading A tiles

        #pragma unroll
        for (int r = 0; r < 16; r++) {
            const int row = gw * 16 + r;
            const int c = lane * 4;
            float4 s = sums[r];
            uint2 hp = make_uint2(pack2(bf_hi(s.x), bf_hi(s.y)), pack2(bf_hi(s.z), bf_hi(s.w)));
            uint2 lp = make_uint2(pack2(bf_lo(s.x), bf_lo(s.y)), pack2(bf_lo(s.z), bf_lo(s.w)));
            *(uint2*)(sm + OFF_AH + row * ASTR + c * 2) = hp;
            *(uint2*)(sm + OFF_AL + row * ASTR + c * 2) = lp;
        }

        BARX(3, THREADS);   // agg published; MMA warps run GEMM3
    }
}

extern "C" void kernel_launch(void* const* d_in, const int* in_sizes, int n_in,
                              void* d_out, int out_size) {
    const float* raw    = (const float*)d_in[0];
    const void*  neigh  = (const void*) d_in[1];
    const float* memory = (const float*)d_in[2];
    const float* W1     = (const float*)d_in[3];
    const float* b1     = (const float*)d_in[4];
    const float* W2     = (const float*)d_in[5];
    const float* b2     = (const float*)d_in[6];
    const float* Wn     = (const float*)d_in[7];
    const float* bn     = (const float*)d_in[8];
    float* out          = (float*)d_out;

    cudaFuncSetAttribute(fused_ws7_kernel,
                         cudaFuncAttributeMaxDynamicSharedMemorySize, SMEM_REQ);

    prep_weights<<<256, 256>>>(W1, W2, Wn, (const long long*)neigh);

    int nblocks = N_SRC / TM;   // 3125 exact
    fused_ws7_kernel<<<nblocks, THREADS, SMEM_REQ>>>(
        raw, neigh, memory, b1, b2, bn, out);
}

// round 17
// speedup vs baseline: 1.1729x; 1.1729x over previous
#include <cuda_runtime.h>
#include <cuda_bf16.h>
#include <cstdint>

#define N_SRC     100000
#define N_NODES   1000000
#define N_NEIGH   20
#define RAW_DIM   256
#define MSG       128

#define TM        32           // 100000 = 32 * 3125 exactly
#define THREADS   192          // 4 MMA warps + 2 gather warps
#define NMMA      128

// gather split: gather warps take rows 0..19 (10 each); MMA warps rows 20..31 (3 each)
#define GROWS     10
#define MROWS     3
#define MROW0     (2 * GROWS)

// A tile: [32 rows][264 bf16] stride 528 B (33*16B -> ldmatrix conflict-free)
#define ASTR      528
// B tiles: [128 k][136 bf16] stride 272 B (17*16B); two buffers, ping-pong
#define BSTR      272

#define OFF_AH    0                     // 32*528 = 16896
#define OFF_AL    16896                 // -> 33792
#define OFF_B0    33792                 // 34816 -> 68608
#define OFF_B1    68608                 // 34816 -> 103424
#define OFF_NEI   103424                // 2560 -> 105984
#define OFF_B1S   105984
#define OFF_B2S   106496
#define OFF_BNS   107008
#define OFF_IS64  107520
#define SMEM_REQ  107536

// pre-converted weights, laid out exactly like the smem B tiles
__device__ __align__(16) __nv_bfloat16 g_W1h[256 * 136];
__device__ __align__(16) __nv_bfloat16 g_W1l[256 * 136];
__device__ __align__(16) __nv_bfloat16 g_W2h[128 * 136];
__device__ __align__(16) __nv_bfloat16 g_W2l[128 * 136];
__device__ __align__(16) __nv_bfloat16 g_Wnh[128 * 136];
__device__ __align__(16) __nv_bfloat16 g_Wnl[128 * 136];

__device__ int g_is64;

__device__ __forceinline__ unsigned short bf_hi(float x) {
    return __bfloat16_as_ushort(__float2bfloat16(x));
}
__device__ __forceinline__ unsigned short bf_lo(float x) {
    __nv_bfloat16 h = __float2bfloat16(x);
    return __bfloat16_as_ushort(__float2bfloat16(x - __bfloat162float(h)));
}
__device__ __forceinline__ uint32_t pack2(unsigned short a, unsigned short b) {
    return (uint32_t)a | ((uint32_t)b << 16);
}

// prep: weight conversion + (block 0, warp 0) index-dtype detection.
__global__ void prep_weights(const float* __restrict__ W1,
                             const float* __restrict__ W2,
                             const float* __restrict__ Wn,
                             const long long* __restrict__ neigh) {
    if (blockIdx.x == 0 && threadIdx.x < 32) {
        int lane = threadIdx.x;
        long long v0 = neigh[lane];
        long long v1 = neigh[lane + 32];
        int bad = (v0 < 0 || v0 >= (long long)N_NODES ||
                   v1 < 0 || v1 >= (long long)N_NODES) ? 1 : 0;
        unsigned m = __ballot_sync(0xFFFFFFFFu, bad);
        if (lane == 0) g_is64 = m ? 0 : 1;
    }
    int i = blockIdx.x * blockDim.x + threadIdx.x;
    if (i < 256 * 128) {
        int r = i >> 7, c = i & 127;
        float v = W1[i];
        g_W1h[r * 136 + c] = __ushort_as_bfloat16(bf_hi(v));
        g_W1l[r * 136 + c] = __ushort_as_bfloat16(bf_lo(v));
    } else if (i < 256 * 128 + 128 * 128) {
        int j = i - 256 * 128;
        int r = j >> 7, c = j & 127;
        float v = W2[j];
        g_W2h[r * 136 + c] = __ushort_as_bfloat16(bf_hi(v));
        g_W2l[r * 136 + c] = __ushort_as_bfloat16(bf_lo(v));
    } else if (i < 256 * 128 + 2 * 128 * 128) {
        int j = i - 256 * 128 - 128 * 128;
        int r = j >> 7, c = j & 127;
        float v = Wn[j];
        g_Wnh[r * 136 + c] = __ushort_as_bfloat16(bf_hi(v));
        g_Wnl[r * 136 + c] = __ushort_as_bfloat16(bf_lo(v));
    }
}

__device__ __forceinline__ uint32_t smem_u32(const void* p) {
    uint32_t a;
    asm("{ .reg .u64 t; cvta.to.shared.u64 t, %1; cvt.u32.u64 %0, t; }" : "=r"(a) : "l"(p));
    return a;
}

#define BARX(id, cnt) asm volatile("bar.sync %0, %1;" :: "r"(id), "r"(cnt) : "memory")
#define CP_COMMIT()   asm volatile("cp.async.commit_group;" ::: "memory")
#define CP_WAIT0()    asm volatile("cp.async.wait_group 0;" ::: "memory")

#define LDSM_X4(r, addr) \
    asm volatile("ldmatrix.sync.aligned.m8n8.x4.shared.b16 {%0,%1,%2,%3}, [%4];" \
        : "=r"((r)[0]), "=r"((r)[1]), "=r"((r)[2]), "=r"((r)[3]) : "r"(addr))

#define LDSM_X4T(r, addr) \
    asm volatile("ldmatrix.sync.aligned.m8n8.x4.trans.shared.b16 {%0,%1,%2,%3}, [%4];" \
        : "=r"((r)[0]), "=r"((r)[1]), "=r"((r)[2]), "=r"((r)[3]) : "r"(addr))

#define MMA16816(ac, a, b0, b1) \
    asm volatile("mma.sync.aligned.m16n8k16.row.col.f32.bf16.bf16.f32 " \
        "{%0,%1,%2,%3}, {%4,%5,%6,%7}, {%8,%9}, {%0,%1,%2,%3};" \
        : "+f"((ac)[0]), "+f"((ac)[1]), "+f"((ac)[2]), "+f"((ac)[3]) \
        : "r"((a)[0]), "r"((a)[1]), "r"((a)[2]), "r"((a)[3]), "r"(b0), "r"(b1))

// async copy of one pre-converted B tile (34816 B) into a smem buffer.
__device__ __forceinline__ void issue_B(uint32_t smem_dst,
                                        const __nv_bfloat16* __restrict__ g,
                                        int k0, int tid) {
    const char* src = (const char*)(g + k0 * 136);
    #pragma unroll
    for (int i = 0; i < 17; i++) {
        int e = tid + i * NMMA;            // 0..2175
        asm volatile("cp.async.cg.shared.global [%0], [%1], 16;"
                     :: "r"(smem_dst + e * 16), "l"(src + (size_t)e * 16));
    }
}

// gather one row's neighbor mean (warp-collective, lane = 4 columns),
// write hi/lo bf16 agg directly into the A tiles.
__device__ __forceinline__ void gather_row_to_A(char* sm, const int* __restrict__ nb,
                                                const float4* __restrict__ mem4,
                                                int row, int lane) {
    float4 s0 = make_float4(0.f, 0.f, 0.f, 0.f);
    float4 s1 = make_float4(0.f, 0.f, 0.f, 0.f);
    #pragma unroll
    for (int j = 0; j < N_NEIGH; j += 2) {
        int nd0 = nb[row * N_NEIGH + j];
        int nd1 = nb[row * N_NEIGH + j + 1];
        float4 v0 = __ldg(&mem4[(size_t)nd0 * 32 + lane]);
        float4 v1 = __ldg(&mem4[(size_t)nd1 * 32 + lane]);
        s0.x += v0.x; s0.y += v0.y; s0.z += v0.z; s0.w += v0.w;
        s1.x += v1.x; s1.y += v1.y; s1.z += v1.z; s1.w += v1.w;
    }
    const float inv = 1.0f / (float)N_NEIGH;
    float4 s = make_float4((s0.x + s1.x) * inv, (s0.y + s1.y) * inv,
                           (s0.z + s1.z) * inv, (s0.w + s1.w) * inv);
    const int c = lane * 4;
    uint2 hp = make_uint2(pack2(bf_hi(s.x), bf_hi(s.y)), pack2(bf_hi(s.z), bf_hi(s.w)));
    uint2 lp = make_uint2(pack2(bf_lo(s.x), bf_lo(s.y)), pack2(bf_lo(s.z), bf_lo(s.w)));
    *(uint2*)(sm + OFF_AH + row * ASTR + c * 2) = hp;
    *(uint2*)(sm + OFF_AL + row * ASTR + c * 2) = lp;
}

// pair product over one K=128 B tile: acc += Ah@B + Al@B
__device__ __forceinline__ void run_pair(
    float acc[8][4], uint32_t sAh, uint32_t sAl, uint32_t sB,
    int lane, int r0, int c0, int aoff)
{
    const int arow = lane & 15;
    const int aka  = (lane >> 4) << 3;
    const int bk   = (lane & 7) + ((lane >> 3) & 1) * 8;
    const int bn   = ((lane >> 4) & 1) * 8;
    #pragma unroll
    for (int ks = 0; ks < 8; ks++) {
        const int k0 = ks * 16;
        uint32_t ah[4], al[4], b[4][4];
        {
            uint32_t off = (uint32_t)((r0 + arow) * ASTR + (aoff + k0 + aka) * 2);
            LDSM_X4(ah, sAh + off);
            LDSM_X4(al, sAl + off);
        }
        #pragma unroll
        for (int ng = 0; ng < 4; ng++) {
            uint32_t off = (uint32_t)((k0 + bk) * BSTR + (c0 + ng * 16 + bn) * 2);
            LDSM_X4T(b[ng], sB + off);
        }
        #pragma unroll
        for (int nt = 0; nt < 8; nt++) {
            const int ng = nt >> 1, s2 = (nt & 1) * 2;
            MMA16816(acc[nt], ah, b[ng][s2], b[ng][s2 + 1]);
            MMA16816(acc[nt], al, b[ng][s2], b[ng][s2 + 1]);
        }
    }
}

// single product: acc += Ah@B
__device__ __forceinline__ void run_single(
    float acc[8][4], uint32_t sAh, uint32_t sB,
    int lane, int r0, int c0, int aoff)
{
    const int arow = lane & 15;
    const int aka  = (lane >> 4) << 3;
    const int bk   = (lane & 7) + ((lane >> 3) & 1) * 8;
    const int bn   = ((lane >> 4) & 1) * 8;
    #pragma unroll
    for (int ks = 0; ks < 8; ks++) {
        const int k0 = ks * 16;
        uint32_t ah[4], b[4][4];
        {
            uint32_t off = (uint32_t)((r0 + arow) * ASTR + (aoff + k0 + aka) * 2);
            LDSM_X4(ah, sAh + off);
        }
        #pragma unroll
        for (int ng = 0; ng < 4; ng++) {
            uint32_t off = (uint32_t)((k0 + bk) * BSTR + (c0 + ng * 16 + bn) * 2);
            LDSM_X4T(b[ng], sB + off);
        }
        #pragma unroll
        for (int nt = 0; nt < 8; nt++) {
            const int ng = nt >> 1, s2 = (nt & 1) * 2;
            MMA16816(acc[nt], ah, b[ng][s2], b[ng][s2 + 1]);
        }
    }
}

// full-K A tile: raw[row0+m][0..255] -> hi/lo bf16, by 128 MMA threads
__device__ __forceinline__ void load_A_full(char* sm, const float* __restrict__ raw,
                                            int row0, int tid) {
    #pragma unroll 4
    for (int i = tid; i < TM * 64; i += NMMA) {
        int m  = i >> 6;
        int k4 = (i & 63) << 2;
        float4 v = *(const float4*)&raw[(size_t)(row0 + m) * RAW_DIM + k4];
        uint2 hp = make_uint2(pack2(bf_hi(v.x), bf_hi(v.y)), pack2(bf_hi(v.z), bf_hi(v.w)));
        uint2 lp = make_uint2(pack2(bf_lo(v.x), bf_lo(v.y)), pack2(bf_lo(v.z), bf_lo(v.w)));
        *(uint2*)(sm + OFF_AH + m * ASTR + k4 * 2) = hp;
        *(uint2*)(sm + OFF_AL + m * ASTR + k4 * 2) = lp;
    }
}

// fp32 'a' staging in the unused upper-K bytes (256..511) of the A tiles
__device__ __forceinline__ uint32_t stg_addr(int li) {
    return (uint32_t)(((li >> 11) ? OFF_AL : OFF_AH)
                      + ((li >> 6) & 31) * ASTR + 256 + (li & 63) * 4);
}

extern __shared__ char sm[];

__global__ __launch_bounds__(THREADS, 2)
void fused_ws8_kernel(
    const float* __restrict__ raw,
    const void*  __restrict__ neigh,
    const float* __restrict__ memory,
    const float* __restrict__ b1,
    const float* __restrict__ b2,
    const float* __restrict__ bn,
    float*       __restrict__ out)
{
    const uint32_t smb = smem_u32(sm);
    const int tid  = threadIdx.x;
    const int lane = tid & 31;
    const int wid  = tid >> 5;
    const int row0 = blockIdx.x * TM;

    if (tid == 0) *(int*)(sm + OFF_IS64) = g_is64;
    if (tid < 128) {
        ((float*)(sm + OFF_B1S))[tid] = b1[tid];
        ((float*)(sm + OFF_B2S))[tid] = b2[tid];
        ((float*)(sm + OFF_BNS))[tid] = bn[tid];
    }
    __syncthreads();

    // ---- neighbor indices -> smem (all threads) ----
    {
        int is64 = *(volatile int*)(sm + OFF_IS64);
        int* nbw = (int*)(sm + OFF_NEI);
        if (is64) {
            const long long* p = (const long long*)neigh;
            for (int i = tid; i < TM * N_NEIGH; i += THREADS)
                nbw[i] = (int)p[(size_t)row0 * N_NEIGH + i];
        } else {
            const int* p = (const int*)neigh;
            for (int i = tid; i < TM * N_NEIGH; i += THREADS)
                nbw[i] = p[(size_t)row0 * N_NEIGH + i];
        }
    }
    __syncthreads();

    const uint32_t AH = smb + OFF_AH, AL = smb + OFF_AL;
    const uint32_t B0 = smb + OFF_B0, B1T = smb + OFF_B1;
    const int* nb = (const int*)(sm + OFF_NEI);
    const float4* mem4 = (const float4*)memory;

    if (wid < 4) {
        // ================== MMA warps (tid 0..127) ==================
        const int r0 = (wid >> 1) * 16;
        const int c0 = (wid & 1) * 64;

        float acc[8][4];
        #pragma unroll
        for (int nt = 0; nt < 8; nt++)
            #pragma unroll
            for (int e = 0; e < 4; e++) acc[nt][e] = 0.f;

        // ---- GEMM1: raw @ W1 (K=256), B tiles ping-ponged via cp.async ----
        issue_B(B0, g_W1h, 0, tid);   CP_COMMIT();
        load_A_full(sm, raw, row0, tid);
        CP_WAIT0(); BARX(1, NMMA);

        issue_B(B1T, g_W1l, 0, tid);  CP_COMMIT();
        run_pair(acc, AH, AL, B0, lane, r0, c0, 0);
        CP_WAIT0(); BARX(1, NMMA);

        issue_B(B0, g_W1h, 128, tid); CP_COMMIT();
        run_single(acc, AH, B1T, lane, r0, c0, 0);
        CP_WAIT0(); BARX(1, NMMA);

        issue_B(B1T, g_W1l, 128, tid); CP_COMMIT();
        run_pair(acc, AH, AL, B0, lane, r0, c0, 128);
        CP_WAIT0(); BARX(1, NMMA);

        issue_B(B0, g_W2h, 0, tid);   CP_COMMIT();
        run_single(acc, AH, B1T, lane, r0, c0, 128);

        // ---- epilogue 1: h = relu(C1 + b1) -> A cols 0..127 ----
        {
            const float* sb1 = (const float*)(sm + OFF_B1S);
            const int qr = lane >> 2, qc = (lane & 3) * 2;
            #pragma unroll
            for (int nt = 0; nt < 8; nt++) {
                int R = r0 + qr;
                int C = c0 + nt * 8 + qc;
                float v0 = fmaxf(acc[nt][0] + sb1[C],     0.f);
                float v1 = fmaxf(acc[nt][1] + sb1[C + 1], 0.f);
                float v2 = fmaxf(acc[nt][2] + sb1[C],     0.f);
                float v3 = fmaxf(acc[nt][3] + sb1[C + 1], 0.f);
                *(uint32_t*)(sm + OFF_AH + R * ASTR + C * 2)       = pack2(bf_hi(v0), bf_hi(v1));
                *(uint32_t*)(sm + OFF_AL + R * ASTR + C * 2)       = pack2(bf_lo(v0), bf_lo(v1));
                *(uint32_t*)(sm + OFF_AH + (R + 8) * ASTR + C * 2) = pack2(bf_hi(v2), bf_hi(v3));
                *(uint32_t*)(sm + OFF_AL + (R + 8) * ASTR + C * 2) = pack2(bf_lo(v2), bf_lo(v3));
                acc[nt][0] = acc[nt][1] = acc[nt][2] = acc[nt][3] = 0.f;
            }
        }
        CP_WAIT0(); BARX(1, NMMA);     // publishes h tiles + W2h

        // ---- GEMM2: h @ W2 ----
        issue_B(B1T, g_W2l, 0, tid);  CP_COMMIT();
        run_pair(acc, AH, AL, B0, lane, r0, c0, 0);
        CP_WAIT0(); BARX(1, NMMA);

        issue_B(B0, g_Wnh, 0, tid);   CP_COMMIT();
        run_single(acc, AH, B1T, lane, r0, c0, 0);
        CP_WAIT0();                    // Wnh landed in B0

        BARX(2, THREADS);   // A tiles free for agg; gather sums ready

        // ---- stage a = relu(C2 + b2) into upper-K bytes ----
        {
            const float* sb2 = (const float*)(sm + OFF_B2S);
            const int qc = (lane & 3) * 2;
            #pragma unroll
            for (int nt = 0; nt < 8; nt++) {
                int C = c0 + nt * 8 + qc;
                *(float*)(sm + stg_addr((nt * 4 + 0) * NMMA + tid)) = fmaxf(acc[nt][0] + sb2[C],     0.f);
                *(float*)(sm + stg_addr((nt * 4 + 1) * NMMA + tid)) = fmaxf(acc[nt][1] + sb2[C + 1], 0.f);
                *(float*)(sm + stg_addr((nt * 4 + 2) * NMMA + tid)) = fmaxf(acc[nt][2] + sb2[C],     0.f);
                *(float*)(sm + stg_addr((nt * 4 + 3) * NMMA + tid)) = fmaxf(acc[nt][3] + sb2[C + 1], 0.f);
                acc[nt][0] = acc[nt][1] = acc[nt][2] = acc[nt][3] = 0.f;
            }
        }
        issue_B(B1T, g_Wnl, 0, tid);  CP_COMMIT();

        // ---- MMA-side gather: 3 rows per warp (rows 20..31) into A tiles ----
        #pragma unroll
        for (int r = 0; r < MROWS; r++)
            gather_row_to_A((char*)sm, nb, mem4, MROW0 + wid * MROWS + r, lane);

        BARX(3, THREADS);   // all agg rows published

        // ---- GEMM3: agg @ Wn ----
        run_pair(acc, AH, AL, B0, lane, r0, c0, 0);
        CP_WAIT0(); BARX(1, NMMA);     // Wnl ready
        run_single(acc, AH, B1T, lane, r0, c0, 0);

        // ---- final: out = a + relu(C3 + bn) ----
        {
            const float* sbn = (const float*)(sm + OFF_BNS);
            const int qr = lane >> 2, qc = (lane & 3) * 2;
            #pragma unroll
            for (int nt = 0; nt < 8; nt++) {
                int R = r0 + qr;
                int C = c0 + nt * 8 + qc;
                float a0 = *(const float*)(sm + stg_addr((nt * 4 + 0) * NMMA + tid));
                float a1 = *(const float*)(sm + stg_addr((nt * 4 + 1) * NMMA + tid));
                float a2 = *(const float*)(sm + stg_addr((nt * 4 + 2) * NMMA + tid));
                float a3 = *(const float*)(sm + stg_addr((nt * 4 + 3) * NMMA + tid));
                float o0 = a0 + fmaxf(acc[nt][0] + sbn[C],     0.f);
                float o1 = a1 + fmaxf(acc[nt][1] + sbn[C + 1], 0.f);
                float o2 = a2 + fmaxf(acc[nt][2] + sbn[C],     0.f);
                float o3 = a3 + fmaxf(acc[nt][3] + sbn[C + 1], 0.f);
                *(float2*)&out[(size_t)(row0 + R) * MSG + C]     = make_float2(o0, o1);
                *(float2*)&out[(size_t)(row0 + R + 8) * MSG + C] = make_float2(o2, o3);
            }
        }
    } else {
        // ================== gather warps (wid 4,5), 10 rows each ==================
        const int gw = wid - 4;

        float4 sums[GROWS];
        #pragma unroll
        for (int r = 0; r < GROWS; r++) {
            const int row = gw * GROWS + r;
            float4 s0 = make_float4(0.f, 0.f, 0.f, 0.f);
            float4 s1 = make_float4(0.f, 0.f, 0.f, 0.f);
            #pragma unroll
            for (int j = 0; j < N_NEIGH; j += 2) {
                int nd0 = nb[row * N_NEIGH + j];
                int nd1 = nb[row * N_NEIGH + j + 1];
                float4 v0 = __ldg(&mem4[(size_t)nd0 * 32 + lane]);
                float4 v1 = __ldg(&mem4[(size_t)nd1 * 32 + lane]);
                s0.x += v0.x; s0.y += v0.y; s0.z += v0.z; s0.w += v0.w;
                s1.x += v1.x; s1.y += v1.y; s1.z += v1.z; s1.w += v1.w;
            }
            const float inv = 1.0f / (float)N_NEIGH;
            sums[r] = make_float4((s0.x + s1.x) * inv, (s0.y + s1.y) * inv,
                                  (s0.z + s1.z) * inv, (s0.w + s1.w) * inv);
        }

        BARX(2, THREADS);   // wait until GEMM2 stops reading A tiles

        #pragma unroll
        for (int r = 0; r < GROWS; r++) {
            const int row = gw * GROWS + r;
            const int c = lane * 4;
            float4 s = sums[r];
            uint2 hp = make_uint2(pack2(bf_hi(s.x), bf_hi(s.y)), pack2(bf_hi(s.z), bf_hi(s.w)));
            uint2 lp = make_uint2(pack2(bf_lo(s.x), bf_lo(s.y)), pack2(bf_lo(s.z), bf_lo(s.w)));
            *(uint2*)(sm + OFF_AH + row * ASTR + c * 2) = hp;
            *(uint2*)(sm + OFF_AL + row * ASTR + c * 2) = lp;
        }

        BARX(3, THREADS);   // agg published; MMA warps run GEMM3
    }
}

extern "C" void kernel_launch(void* const* d_in, const int* in_sizes, int n_in,
                              void* d_out, int out_size) {
    const float* raw    = (const float*)d_in[0];
    const void*  neigh  = (const void*) d_in[1];
    const float* memory = (const float*)d_in[2];
    const float* W1     = (const float*)d_in[3];
    const float* b1     = (const float*)d_in[4];
    const float* W2     = (const float*)d_in[5];
    const float* b2     = (const float*)d_in[6];
    const float* Wn     = (const float*)d_in[7];
    const float* bn     = (const float*)d_in[8];
    float* out          = (float*)d_out;

    cudaFuncSetAttribute(fused_ws8_kernel,
                         cudaFuncAttributeMaxDynamicSharedMemorySize, SMEM_REQ);

    prep_weights<<<256, 256>>>(W1, W2, Wn, (const long long*)neigh);

    int nblocks = N_SRC / TM;   // 3125 exact
    fused_ws8_kernel<<<nblocks, THREADS, SMEM_REQ>>>(
        raw, neigh, memory, b1, b2, bn, out);
}